// round 8
// baseline (speedup 1.0000x reference)
#include <cuda_runtime.h>
#include <cstdint>

#define TS   2048
#define TDK  64
#define TB   2
#define TH   16
#define TBH  (TB*TH)
#define CTX_ELEMS (TBH*TS*TDK)          /* 4,194,304  */

// ---------------- device scratch ---------------------------------------------
__device__ float2 g_part[TBH * TS * 16];   // per (row, ktile): (max, sumexp_tile)
__device__ float  g_scale[TBH * TS * 16];  // per (row, ktile): exp(mx_t-m)/S

// ---------------- packed f32x2 helpers ---------------------------------------
__device__ __forceinline__ unsigned long long fma2(unsigned long long a,
                                                   unsigned long long b,
                                                   unsigned long long c) {
    unsigned long long d;
    asm("fma.rn.f32x2 %0, %1, %2, %3;" : "=l"(d) : "l"(a), "l"(b), "l"(c));
    return d;
}
__device__ __forceinline__ unsigned long long dup2(float s) {
    unsigned long long d;
    asm("mov.b64 %0, {%1, %1};" : "=l"(d) : "f"(s));
    return d;
}
__device__ __forceinline__ float2 unpk(unsigned long long v) {
    float2 r;
    asm("mov.b64 {%0, %1}, %2;" : "=f"(r.x), "=f"(r.y) : "l"(v));
    return r;
}

// ---------------- JAX threefry2x32 (key = (0, 42)), partitionable ------------
__device__ __forceinline__ void tf_round(unsigned& x0, unsigned& x1, int r) {
    x0 += x1;
    x1 = __funnelshift_l(x1, x1, r);
    x1 ^= x0;
}
__device__ __forceinline__ unsigned tf_bits(unsigned c1) {
    const unsigned k0 = 0u, k1 = 42u, k2 = 0x1BD11BDAu ^ 42u;
    unsigned x0 = 0u + k0, x1 = c1 + k1;
    tf_round(x0,x1,13); tf_round(x0,x1,15); tf_round(x0,x1,26); tf_round(x0,x1, 6);
    x0 += k1; x1 += k2 + 1u;
    tf_round(x0,x1,17); tf_round(x0,x1,29); tf_round(x0,x1,16); tf_round(x0,x1,24);
    x0 += k2; x1 += k0 + 2u;
    tf_round(x0,x1,13); tf_round(x0,x1,15); tf_round(x0,x1,26); tf_round(x0,x1, 6);
    x0 += k0; x1 += k1 + 3u;
    tf_round(x0,x1,17); tf_round(x0,x1,29); tf_round(x0,x1,16); tf_round(x0,x1,24);
    x0 += k1; x1 += k2 + 4u;
    tf_round(x0,x1,13); tf_round(x0,x1,15); tf_round(x0,x1,26); tf_round(x0,x1, 6);
    x0 += k2; x1 += k0 + 5u;
    return x0 ^ x1;   // 32-bit combine
}
// 2.0 if kept (inverse keep-prob), 0.0 if dropped: uniform<0.5 <=> MSB clear
__device__ __forceinline__ float keep2x(unsigned e) {
    return ((~tf_bits(e)) >> 31) ? 2.0f : 0.0f;
}

// ---------------- K1: tile-exp'd scores + per-(row,ktile) stats --------------
// 64q x 128k tile, 256 threads, 3 blocks/SM. Warp: tx=tid&31 owns k=tx*4,
// ty=tid>>5, q=ty+8j. b-operand LDS double-buffered across c-chunks.
// Stores exp(s - mx_tile) into the attn buffer (K3 rescales, no exp there).
__global__ __launch_bounds__(256, 3) void scores_kernel(
    const float* __restrict__ Q, const float* __restrict__ Km,
    const float* __restrict__ mask, float* __restrict__ scores) {
    extern __shared__ float sm[];
    float* Qs = sm;            // [64][68]
    float* Kt = sm + 64 * 68;  // [64][132]  d-major

    const int bh    = blockIdx.z;
    const int b     = bh >> 4;
    const int qBase = blockIdx.y * 64;
    const int kBase = blockIdx.x * 128;
    const int tid   = threadIdx.x;

    const float* Qg = Q  + ((size_t)bh * TS + qBase) * TDK;
    const float* Kg = Km + ((size_t)bh * TS + kBase) * TDK;

#pragma unroll
    for (int i = 0; i < 4; i++) {
        int f = tid + i * 256, r = f >> 4, c4 = f & 15;
        *(float4*)(Qs + r * 68 + c4 * 4) = *(const float4*)(Qg + r * 64 + c4 * 4);
    }
#pragma unroll
    for (int i = 0; i < 8; i++) {
        int f = tid + i * 256, r = f >> 4, c4 = f & 15;   // r = k row 0..127
        float4 kv = *(const float4*)(Kg + r * 64 + c4 * 4);
#pragma unroll
        for (int u = 0; u < 4; u++) {
            int d = c4 * 4 + u;
            int s = ((d >> 3) & 3) << 3;
            float vv = (u == 0) ? kv.x : (u == 1) ? kv.y : (u == 2) ? kv.z : kv.w;
            Kt[d * 132 + (r ^ s)] = vv;
        }
    }
    __syncthreads();

    const int tx = tid & 31, ty = tid >> 5;

    unsigned long long acc[8][2];
#pragma unroll
    for (int j = 0; j < 8; j++) { acc[j][0] = 0ull; acc[j][1] = 0ull; }

    ulonglong2 bb[4];
#pragma unroll
    for (int dd = 0; dd < 4; dd++) {
        int s = ((dd >> 3) & 3) << 3;
        bb[dd] = *(const ulonglong2*)(Kt + dd * 132 + ((tx << 2) ^ s));
    }

#pragma unroll
    for (int c = 0; c < 16; c++) {
        ulonglong2 nb[4];
        if (c < 15) {
#pragma unroll
            for (int dd = 0; dd < 4; dd++) {
                int d = (c + 1) * 4 + dd;
                int s = ((d >> 3) & 3) << 3;
                nb[dd] = *(const ulonglong2*)(Kt + d * 132 + ((tx << 2) ^ s));
            }
        }
#pragma unroll
        for (int j = 0; j < 8; j++) {
            float4 a = *(const float4*)(Qs + (ty + 8 * j) * 68 + c * 4);
            unsigned long long a0 = dup2(a.x), a1 = dup2(a.y);
            unsigned long long a2 = dup2(a.z), a3 = dup2(a.w);
            acc[j][0] = fma2(a0, bb[0].x, acc[j][0]);
            acc[j][1] = fma2(a0, bb[0].y, acc[j][1]);
            acc[j][0] = fma2(a1, bb[1].x, acc[j][0]);
            acc[j][1] = fma2(a1, bb[1].y, acc[j][1]);
            acc[j][0] = fma2(a2, bb[2].x, acc[j][0]);
            acc[j][1] = fma2(a2, bb[2].y, acc[j][1]);
            acc[j][0] = fma2(a3, bb[3].x, acc[j][0]);
            acc[j][1] = fma2(a3, bb[3].y, acc[j][1]);
        }
        if (c < 15) {
#pragma unroll
            for (int dd = 0; dd < 4; dd++) bb[dd] = nb[dd];
        }
    }

    // epilogue: mask, tile max, store exp(s - mx_tile), tile stats
    const float* mrow = mask + (size_t)b * TS * TS;
#pragma unroll
    for (int j = 0; j < 8; j++) {
        int q = qBase + ty + 8 * j;
        float4 m0 = *(const float4*)(mrow + (size_t)q * TS + kBase + tx * 4);
        float2 p0 = unpk(acc[j][0]), p1 = unpk(acc[j][1]);
        float s0 = fmaf(p0.x, 0.125f, (m0.x - 1.0f) * 1e9f);
        float s1 = fmaf(p0.y, 0.125f, (m0.y - 1.0f) * 1e9f);
        float s2 = fmaf(p1.x, 0.125f, (m0.z - 1.0f) * 1e9f);
        float s3 = fmaf(p1.y, 0.125f, (m0.w - 1.0f) * 1e9f);

        float mx = fmaxf(fmaxf(s0, s1), fmaxf(s2, s3));
#pragma unroll
        for (int o = 16; o > 0; o >>= 1)
            mx = fmaxf(mx, __shfl_xor_sync(0xffffffffu, mx, o));
        float t0 = __expf(s0 - mx), t1 = __expf(s1 - mx);
        float t2 = __expf(s2 - mx), t3 = __expf(s3 - mx);
        *(float4*)(scores + ((size_t)bh * TS + q) * TS + kBase + tx * 4) =
            make_float4(t0, t1, t2, t3);
        float e = t0 + t1 + t2 + t3;
#pragma unroll
        for (int o = 16; o > 0; o >>= 1)
            e += __shfl_xor_sync(0xffffffffu, e, o);
        if (tx == 0)
            g_part[((size_t)bh * TS + q) * 16 + blockIdx.x] = make_float2(mx, e);
    }
}

// ---------------- K2: tile partials -> per-(row,ktile) rescale factors -------
__global__ __launch_bounds__(256) void reduce_kernel() {
    unsigned row = blockIdx.x * 256u + threadIdx.x;   // 0 .. 65535
    const float2* pp = &g_part[(size_t)row * 16];
    float2 p[16];
#pragma unroll
    for (int t = 0; t < 16; t++) p[t] = pp[t];
    float m = p[0].x;
#pragma unroll
    for (int t = 1; t < 16; t++) m = fmaxf(m, p[t].x);
    float s = 0.f;
#pragma unroll
    for (int t = 0; t < 16; t++) s += p[t].y * __expf(p[t].x - m);
    float inv = 1.0f / s;
#pragma unroll
    for (int t = 0; t < 16; t++)
        g_scale[(size_t)row * 16 + t] = __expf(p[t].x - m) * inv;
}

// ---------------- K3: attn rescale + inline-RNG dropout + (P_drop @ V) -------
// 64q x 64dv tile, 512 threads, 2 blocks/SM (32 warps/SM). No exp here:
// attn = t_tile * g_scale[row][ktile]. RNG drawn inline while staging.
__global__ __launch_bounds__(512, 2) void context_kernel(
    const float* __restrict__ V, float* __restrict__ attn, float* __restrict__ ctx) {
    extern __shared__ float sm[];
    float* Ps  = sm;                       // [64][68]
    float* Vs  = sm + 64 * 68;             // [64][68]
    float* scs = sm + 128 * 68;            // [64][16]

    const int bh    = blockIdx.z;
    const int qBase = blockIdx.x * 64;
    const int tid   = threadIdx.x;
    const int tx    = tid & 15, ty = tid >> 4;   // ty 0..31

#pragma unroll
    for (int i = 0; i < 2; i++) {
        int x = tid + i * 512;   // 0..1023 = 64 rows x 16 tiles
        scs[x] = g_scale[((size_t)bh * TS + qBase + (x >> 4)) * 16 + (x & 15)];
    }
    __syncthreads();

    unsigned long long acc2[2][2];
#pragma unroll
    for (int j = 0; j < 2; j++) { acc2[j][0] = 0ull; acc2[j][1] = 0ull; }

    const float* Vg = V + (size_t)bh * TS * TDK;

    for (int c = 0; c < 32; c++) {
        int kBase = c * 64;
#pragma unroll
        for (int i = 0; i < 2; i++) {
            int f = tid + i * 512, r = f >> 4, c4 = f & 15;
            int q = qBase + r, k = kBase + c4 * 4;
            size_t off = ((size_t)bh * TS + q) * TS + k;
            unsigned e0 = ((unsigned)(bh * TS + q)) * (unsigned)TS + (unsigned)k;
            float4 tv = *(const float4*)(attn + off);
            float sc = scs[r * 16 + (c >> 1)];
            float4 p;
            p.x = tv.x * sc; p.y = tv.y * sc; p.z = tv.z * sc; p.w = tv.w * sc;
            *(float4*)(attn + off) = p;               // normalized attn out
            float4 pd;
            pd.x = p.x * keep2x(e0);
            pd.y = p.y * keep2x(e0 + 1u);
            pd.z = p.z * keep2x(e0 + 2u);
            pd.w = p.w * keep2x(e0 + 3u);
            *(float4*)(Ps + r * 68 + c4 * 4) = pd;

            *(float4*)(Vs + r * 68 + c4 * 4) =
                *(const float4*)(Vg + (size_t)(kBase + r) * TDK + c4 * 4);
        }
        __syncthreads();
#pragma unroll
        for (int kk4 = 0; kk4 < 16; kk4++) {
            float4 av[2];
#pragma unroll
            for (int j = 0; j < 2; j++)
                av[j] = *(const float4*)(Ps + (ty + 32 * j) * 68 + kk4 * 4);
#pragma unroll
            for (int t = 0; t < 4; t++) {
                ulonglong2 bv = *(const ulonglong2*)(Vs + (kk4 * 4 + t) * 68 + tx * 4);
#pragma unroll
                for (int j = 0; j < 2; j++) {
                    float as = (t == 0) ? av[j].x : (t == 1) ? av[j].y :
                               (t == 2) ? av[j].z : av[j].w;
                    unsigned long long a2 = dup2(as);
                    acc2[j][0] = fma2(a2, bv.x, acc2[j][0]);
                    acc2[j][1] = fma2(a2, bv.y, acc2[j][1]);
                }
            }
        }
        __syncthreads();
    }

#pragma unroll
    for (int j = 0; j < 2; j++) {
        int q = qBase + ty + 32 * j;
        float2 lo = unpk(acc2[j][0]), hi = unpk(acc2[j][1]);
        *(float4*)(ctx + ((size_t)bh * TS + q) * TDK + tx * 4) =
            make_float4(lo.x, lo.y, hi.x, hi.y);
    }
}

// ---------------- launch -----------------------------------------------------
extern "C" void kernel_launch(void* const* d_in, const int* in_sizes, int n_in,
                              void* d_out, int out_size) {
    const float* Q    = (const float*)d_in[0];
    const float* K    = (const float*)d_in[1];
    const float* V    = (const float*)d_in[2];
    const float* mask = (const float*)d_in[3];

    float* ctx  = (float*)d_out;            // context first (reference return order)
    float* attn = ctx + CTX_ELEMS;          // then attn; also used as scores scratch

    cudaFuncSetAttribute(scores_kernel,  cudaFuncAttributeMaxDynamicSharedMemorySize, 51200);
    cudaFuncSetAttribute(context_kernel, cudaFuncAttributeMaxDynamicSharedMemorySize, 39424);

    scores_kernel<<<dim3(16, 32, 32), 256, 51200>>>(Q, K, mask, attn);
    reduce_kernel<<<256, 256>>>();
    context_kernel<<<dim3(32, 1, 32), 512, 39424>>>(V, attn, ctx);
}

// round 9
// speedup vs baseline: 1.8962x; 1.8962x over previous
#include <cuda_runtime.h>
#include <cstdint>

#define TS   2048
#define TDK  64
#define TB   2
#define TH   16
#define TBH  (TB*TH)
#define CTX_ELEMS (TBH*TS*TDK)          /* 4,194,304  */

// ---------------- device scratch ---------------------------------------------
__device__ float2 g_part[TBH * TS * 16];   // per (row, ktile): (max, sumexp_tile)
__device__ float  g_scale[TBH * TS * 16];  // per (row, ktile): exp(mx_t-m)/S

// ---------------- packed f32x2 helpers ---------------------------------------
__device__ __forceinline__ unsigned long long fma2(unsigned long long a,
                                                   unsigned long long b,
                                                   unsigned long long c) {
    unsigned long long d;
    asm("fma.rn.f32x2 %0, %1, %2, %3;" : "=l"(d) : "l"(a), "l"(b), "l"(c));
    return d;
}
__device__ __forceinline__ unsigned long long dup2(float s) {
    unsigned long long d;
    asm("mov.b64 %0, {%1, %1};" : "=l"(d) : "f"(s));
    return d;
}
__device__ __forceinline__ float2 unpk(unsigned long long v) {
    float2 r;
    asm("mov.b64 {%0, %1}, %2;" : "=f"(r.x), "=f"(r.y) : "l"(v));
    return r;
}

// ---------------- JAX threefry2x32 (key = (0, 42)), partitionable ------------
__device__ __forceinline__ void tf_round(unsigned& x0, unsigned& x1, int r) {
    x0 += x1;
    x1 = __funnelshift_l(x1, x1, r);
    x1 ^= x0;
}
__device__ __forceinline__ unsigned tf_bits(unsigned c1) {
    const unsigned k0 = 0u, k1 = 42u, k2 = 0x1BD11BDAu ^ 42u;
    unsigned x0 = 0u + k0, x1 = c1 + k1;
    tf_round(x0,x1,13); tf_round(x0,x1,15); tf_round(x0,x1,26); tf_round(x0,x1, 6);
    x0 += k1; x1 += k2 + 1u;
    tf_round(x0,x1,17); tf_round(x0,x1,29); tf_round(x0,x1,16); tf_round(x0,x1,24);
    x0 += k2; x1 += k0 + 2u;
    tf_round(x0,x1,13); tf_round(x0,x1,15); tf_round(x0,x1,26); tf_round(x0,x1, 6);
    x0 += k0; x1 += k1 + 3u;
    tf_round(x0,x1,17); tf_round(x0,x1,29); tf_round(x0,x1,16); tf_round(x0,x1,24);
    x0 += k1; x1 += k2 + 4u;
    tf_round(x0,x1,13); tf_round(x0,x1,15); tf_round(x0,x1,26); tf_round(x0,x1, 6);
    x0 += k2; x1 += k0 + 5u;
    return x0 ^ x1;   // 32-bit combine
}
// 2.0 if kept (inverse keep-prob), 0.0 if dropped: uniform<0.5 <=> MSB clear
__device__ __forceinline__ float keep2x(unsigned e) {
    return ((~tf_bits(e)) >> 31) ? 2.0f : 0.0f;
}

// ---------------- K1: tile-exp'd scores + per-(row,ktile) stats --------------
// 64q x 128k tile, 256 threads, 3 blocks/SM (round-7 structure, NO double
// buffering). Warp: tx=tid&31 owns k=tx*4 (2 f32x2 pairs), ty=tid>>5,
// q=ty+8j. Stores exp(s - mx_tile); K3 rescales with g_scale (no exp there).
__global__ __launch_bounds__(256, 3) void scores_kernel(
    const float* __restrict__ Q, const float* __restrict__ Km,
    const float* __restrict__ mask, float* __restrict__ scores) {
    extern __shared__ float sm[];
    float* Qs = sm;            // [64][68]
    float* Kt = sm + 64 * 68;  // [64][132]  d-major

    const int bh    = blockIdx.z;
    const int b     = bh >> 4;
    const int qBase = blockIdx.y * 64;
    const int kBase = blockIdx.x * 128;
    const int tid   = threadIdx.x;

    const float* Qg = Q  + ((size_t)bh * TS + qBase) * TDK;
    const float* Kg = Km + ((size_t)bh * TS + kBase) * TDK;

#pragma unroll
    for (int i = 0; i < 4; i++) {
        int f = tid + i * 256, r = f >> 4, c4 = f & 15;
        *(float4*)(Qs + r * 68 + c4 * 4) = *(const float4*)(Qg + r * 64 + c4 * 4);
    }
#pragma unroll
    for (int i = 0; i < 8; i++) {
        int f = tid + i * 256, r = f >> 4, c4 = f & 15;   // r = k row 0..127
        float4 kv = *(const float4*)(Kg + r * 64 + c4 * 4);
#pragma unroll
        for (int u = 0; u < 4; u++) {
            int d = c4 * 4 + u;
            int s = ((d >> 3) & 3) << 3;
            float vv = (u == 0) ? kv.x : (u == 1) ? kv.y : (u == 2) ? kv.z : kv.w;
            Kt[d * 132 + (r ^ s)] = vv;
        }
    }
    __syncthreads();

    const int tx = tid & 31, ty = tid >> 5;

    unsigned long long acc[8][2];
#pragma unroll
    for (int j = 0; j < 8; j++) { acc[j][0] = 0ull; acc[j][1] = 0ull; }

#pragma unroll
    for (int c = 0; c < 16; c++) {
        ulonglong2 bb[4];
#pragma unroll
        for (int dd = 0; dd < 4; dd++) {
            int d = c * 4 + dd;
            int s = ((d >> 3) & 3) << 3;
            bb[dd] = *(const ulonglong2*)(Kt + d * 132 + ((tx << 2) ^ s));
        }
#pragma unroll
        for (int j = 0; j < 8; j++) {
            float4 a = *(const float4*)(Qs + (ty + 8 * j) * 68 + c * 4);
            unsigned long long a0 = dup2(a.x), a1 = dup2(a.y);
            unsigned long long a2 = dup2(a.z), a3 = dup2(a.w);
            acc[j][0] = fma2(a0, bb[0].x, acc[j][0]);
            acc[j][1] = fma2(a0, bb[0].y, acc[j][1]);
            acc[j][0] = fma2(a1, bb[1].x, acc[j][0]);
            acc[j][1] = fma2(a1, bb[1].y, acc[j][1]);
            acc[j][0] = fma2(a2, bb[2].x, acc[j][0]);
            acc[j][1] = fma2(a2, bb[2].y, acc[j][1]);
            acc[j][0] = fma2(a3, bb[3].x, acc[j][0]);
            acc[j][1] = fma2(a3, bb[3].y, acc[j][1]);
        }
    }

    // epilogue: mask, tile max, store exp(s - mx_tile), tile stats
    const float* mrow = mask + (size_t)b * TS * TS;
#pragma unroll
    for (int j = 0; j < 8; j++) {
        int q = qBase + ty + 8 * j;
        float4 m0 = *(const float4*)(mrow + (size_t)q * TS + kBase + tx * 4);
        float2 p0 = unpk(acc[j][0]), p1 = unpk(acc[j][1]);
        float s0 = fmaf(p0.x, 0.125f, (m0.x - 1.0f) * 1e9f);
        float s1 = fmaf(p0.y, 0.125f, (m0.y - 1.0f) * 1e9f);
        float s2 = fmaf(p1.x, 0.125f, (m0.z - 1.0f) * 1e9f);
        float s3 = fmaf(p1.y, 0.125f, (m0.w - 1.0f) * 1e9f);

        float mx = fmaxf(fmaxf(s0, s1), fmaxf(s2, s3));
#pragma unroll
        for (int o = 16; o > 0; o >>= 1)
            mx = fmaxf(mx, __shfl_xor_sync(0xffffffffu, mx, o));
        float t0 = __expf(s0 - mx), t1 = __expf(s1 - mx);
        float t2 = __expf(s2 - mx), t3 = __expf(s3 - mx);
        *(float4*)(scores + ((size_t)bh * TS + q) * TS + kBase + tx * 4) =
            make_float4(t0, t1, t2, t3);
        float e = t0 + t1 + t2 + t3;
#pragma unroll
        for (int o = 16; o > 0; o >>= 1)
            e += __shfl_xor_sync(0xffffffffu, e, o);
        if (tx == 0)
            g_part[((size_t)bh * TS + q) * 16 + blockIdx.x] = make_float2(mx, e);
    }
}

// ---------------- K2: tile partials -> per-(row,ktile) rescale factors -------
__global__ __launch_bounds__(256) void reduce_kernel() {
    unsigned row = blockIdx.x * 256u + threadIdx.x;   // 0 .. 65535
    const float2* pp = &g_part[(size_t)row * 16];
    float2 p[16];
#pragma unroll
    for (int t = 0; t < 16; t++) p[t] = pp[t];
    float m = p[0].x;
#pragma unroll
    for (int t = 1; t < 16; t++) m = fmaxf(m, p[t].x);
    float s = 0.f;
#pragma unroll
    for (int t = 0; t < 16; t++) s += p[t].y * __expf(p[t].x - m);
    float inv = 1.0f / s;
#pragma unroll
    for (int t = 0; t < 16; t++)
        g_scale[(size_t)row * 16 + t] = __expf(p[t].x - m) * inv;
}

// ---------------- K3: attn rescale + inline-RNG dropout + (P_drop @ V) -------
// 64q x 64dv tile, 256 threads, 3 blocks/SM (round-7 shape). No exp here:
// attn = t_tile * g_scale[row][ktile]. RNG drawn inline while staging.
__global__ __launch_bounds__(256, 3) void context_kernel(
    const float* __restrict__ V, float* __restrict__ attn, float* __restrict__ ctx) {
    extern __shared__ float sm[];
    float* Ps  = sm;                       // [64][68]
    float* Vs  = sm + 64 * 68;             // [64][68]
    float* scs = sm + 128 * 68;            // [64][16]

    const int bh    = blockIdx.z;
    const int qBase = blockIdx.x * 64;
    const int tid   = threadIdx.x;
    const int tx    = tid & 15, ty = tid >> 4;

#pragma unroll
    for (int i = 0; i < 4; i++) {
        int x = tid + i * 256;   // 0..1023 = 64 rows x 16 tiles
        scs[x] = g_scale[((size_t)bh * TS + qBase + (x >> 4)) * 16 + (x & 15)];
    }
    __syncthreads();

    unsigned long long acc2[4][2];
#pragma unroll
    for (int j = 0; j < 4; j++) { acc2[j][0] = 0ull; acc2[j][1] = 0ull; }

    const float* Vg = V + (size_t)bh * TS * TDK;

    for (int c = 0; c < 32; c++) {
        int kBase = c * 64;
#pragma unroll
        for (int i = 0; i < 4; i++) {
            int f = tid + i * 256, r = f >> 4, c4 = f & 15;
            int q = qBase + r, k = kBase + c4 * 4;
            size_t off = ((size_t)bh * TS + q) * TS + k;
            unsigned e0 = ((unsigned)(bh * TS + q)) * (unsigned)TS + (unsigned)k;
            float4 tv = *(const float4*)(attn + off);
            float sc = scs[r * 16 + (c >> 1)];
            float4 p;
            p.x = tv.x * sc; p.y = tv.y * sc; p.z = tv.z * sc; p.w = tv.w * sc;
            *(float4*)(attn + off) = p;               // normalized attn out
            float4 pd;
            pd.x = p.x * keep2x(e0);
            pd.y = p.y * keep2x(e0 + 1u);
            pd.z = p.z * keep2x(e0 + 2u);
            pd.w = p.w * keep2x(e0 + 3u);
            *(float4*)(Ps + r * 68 + c4 * 4) = pd;

            *(float4*)(Vs + r * 68 + c4 * 4) =
                *(const float4*)(Vg + (size_t)(kBase + r) * TDK + c4 * 4);
        }
        __syncthreads();
#pragma unroll
        for (int kk4 = 0; kk4 < 16; kk4++) {
            float4 av[4];
#pragma unroll
            for (int j = 0; j < 4; j++)
                av[j] = *(const float4*)(Ps + (ty + 16 * j) * 68 + kk4 * 4);
#pragma unroll
            for (int t = 0; t < 4; t++) {
                ulonglong2 bv = *(const ulonglong2*)(Vs + (kk4 * 4 + t) * 68 + tx * 4);
#pragma unroll
                for (int j = 0; j < 4; j++) {
                    float as = (t == 0) ? av[j].x : (t == 1) ? av[j].y :
                               (t == 2) ? av[j].z : av[j].w;
                    unsigned long long a2 = dup2(as);
                    acc2[j][0] = fma2(a2, bv.x, acc2[j][0]);
                    acc2[j][1] = fma2(a2, bv.y, acc2[j][1]);
                }
            }
        }
        __syncthreads();
    }

#pragma unroll
    for (int j = 0; j < 4; j++) {
        int q = qBase + ty + 16 * j;
        float2 lo = unpk(acc2[j][0]), hi = unpk(acc2[j][1]);
        *(float4*)(ctx + ((size_t)bh * TS + q) * TDK + tx * 4) =
            make_float4(lo.x, lo.y, hi.x, hi.y);
    }
}

// ---------------- launch -----------------------------------------------------
extern "C" void kernel_launch(void* const* d_in, const int* in_sizes, int n_in,
                              void* d_out, int out_size) {
    const float* Q    = (const float*)d_in[0];
    const float* K    = (const float*)d_in[1];
    const float* V    = (const float*)d_in[2];
    const float* mask = (const float*)d_in[3];

    float* ctx  = (float*)d_out;            // context first (reference return order)
    float* attn = ctx + CTX_ELEMS;          // then attn; also used as scores scratch

    cudaFuncSetAttribute(scores_kernel,  cudaFuncAttributeMaxDynamicSharedMemorySize, 51200);
    cudaFuncSetAttribute(context_kernel, cudaFuncAttributeMaxDynamicSharedMemorySize, 38912);

    scores_kernel<<<dim3(16, 32, 32), 256, 51200>>>(Q, K, mask, attn);
    reduce_kernel<<<256, 256>>>();
    context_kernel<<<dim3(32, 1, 32), 256, 38912>>>(V, attn, ctx);
}